// round 7
// baseline (speedup 1.0000x reference)
#include <cuda_runtime.h>
#include <cuda_bf16.h>

// Problem constants: B=4, L=1024, E=256, S=32, W=2S+1=65
#define BB 4
#define LL 1024
#define EE 256
#define NW (EE * EE)
#define LOG2E 1.4426950408889634f

// Device-global scratch (no allocations allowed)
__device__ float g_Q[BB * LL * EE];
__device__ float g_K[BB * LL * EE];
__device__ float g_V[BB * LL * EE];

// ---------------------------------------------------------------------------
// helpers
// ---------------------------------------------------------------------------
__device__ __forceinline__ float ex2f(float x) {
    float r; asm("ex2.approx.f32 %0, %1;" : "=f"(r) : "f"(x)); return r;
}
__device__ __forceinline__ float rcpf(float x) {
    float r; asm("rcp.approx.f32 %0, %1;" : "=f"(r) : "f"(x)); return r;
}
__device__ __forceinline__ void ldsm4(unsigned* r, unsigned addr) {
    asm volatile("ldmatrix.sync.aligned.m8n8.x4.shared.b16 {%0,%1,%2,%3}, [%4];"
                 : "=r"(r[0]), "=r"(r[1]), "=r"(r[2]), "=r"(r[3]) : "r"(addr));
}
__device__ __forceinline__ void mma16816(float* c, const unsigned* a, const unsigned* b) {
    asm volatile(
        "mma.sync.aligned.m16n8k16.row.col.f32.bf16.bf16.f32 "
        "{%0,%1,%2,%3},{%4,%5,%6,%7},{%8,%9},{%0,%1,%2,%3};"
        : "+f"(c[0]), "+f"(c[1]), "+f"(c[2]), "+f"(c[3])
        : "r"(a[0]), "r"(a[1]), "r"(a[2]), "r"(a[3]), "r"(b[0]), "r"(b[1]));
}

// Convert 8 fp32 -> 8 bf16 hi + 8 bf16 lo (residual); store as uint4 pairs.
__device__ __forceinline__ void cvt8store(__nv_bfloat16* dh, __nv_bfloat16* dl,
                                          float4 a, float4 b) {
    float v[8] = {a.x, a.y, a.z, a.w, b.x, b.y, b.z, b.w};
    __nv_bfloat16 h[8], l[8];
    #pragma unroll
    for (int j = 0; j < 8; ++j) {
        h[j] = __float2bfloat16(v[j]);
        l[j] = __float2bfloat16(v[j] - __bfloat162float(h[j]));
    }
    *(uint4*)dh = *(uint4*)h;
    *(uint4*)dl = *(uint4*)l;
}

// ---------------------------------------------------------------------------
// Kernel 1: QKV projection via tensor cores, with the fp32 -> bf16 hi/lo
// split FUSED into the load stage (fp32 tile and hi+lo bf16 tiles are the
// same byte count, so this is traffic-neutral and kills the cvt kernel).
// out[m][n] = sum_k A[m][k]*W[n][k] + bias[n], 3-term split (hh + hl + lh).
// Block: 256 thr (8 warps, 4x2), BM=128, BN=64, BK=32; smem pitch 40 bf16.
// Prefetch pipeline: global loads for kt+1 issued before compute of kt.
// grid = (32, 4, 3)
// ---------------------------------------------------------------------------
__global__ __launch_bounds__(256, 2) void qkv_mma(
    const float* __restrict__ A,
    const float* __restrict__ W0, const float* __restrict__ W1,
    const float* __restrict__ W2,
    const float* __restrict__ bq, const float* __restrict__ bk,
    const float* __restrict__ bv)
{
    __shared__ __align__(16) __nv_bfloat16 sA[2][128 * 40];  // [hi/lo][row][k]
    __shared__ __align__(16) __nv_bfloat16 sW[2][64 * 40];

    const int tid = threadIdx.x;
    const int z  = blockIdx.z;
    const int m0 = blockIdx.x * 128;
    const int n0 = blockIdx.y * 64;
    const float* Wm = (z == 0) ? W0 : (z == 1) ? W1 : W2;

    const int lane = tid & 31, wid = tid >> 5;
    const int wm = wid & 3;
    const int wn = wid >> 2;

    const int lr  = tid >> 2;            // 0..63 (row)
    const int lkf = (tid & 3) * 8;       // fp32 col offset: 0,8,16,24

    float acc[2][4][4];
    #pragma unroll
    for (int mt = 0; mt < 2; ++mt)
        #pragma unroll
        for (int nt = 0; nt < 4; ++nt)
            #pragma unroll
            for (int r = 0; r < 4; ++r) acc[mt][nt][r] = 0.0f;

    // ldmatrix lane addressing
    const int mat = lane >> 3;
    const int a_m = (mat & 1) * 8 + (lane & 7);
    const int a_k = (mat >> 1) * 8;
    const int w_n = (mat >> 1) * 8 + (lane & 7);
    const int w_k = (mat & 1) * 8;

    // prefetch registers: 6 float4 per k-tile
    float4 pa0a, pa0b, pa1a, pa1b, pw0a, pw0b;
    {
        const float* pA0 = &A [(m0 +      lr) * EE + lkf];
        const float* pA1 = &A [(m0 + 64 + lr) * EE + lkf];
        const float* pW  = &Wm[(n0 +      lr) * EE + lkf];
        pa0a = *(const float4*)(pA0);     pa0b = *(const float4*)(pA0 + 4);
        pa1a = *(const float4*)(pA1);     pa1b = *(const float4*)(pA1 + 4);
        pw0a = *(const float4*)(pW);      pw0b = *(const float4*)(pW + 4);
    }

    for (int kt = 0; kt < 8; ++kt) {
        __syncthreads();   // previous tile fully consumed
        cvt8store(&sA[0][lr * 40 + lkf],        &sA[1][lr * 40 + lkf],        pa0a, pa0b);
        cvt8store(&sA[0][(64 + lr) * 40 + lkf], &sA[1][(64 + lr) * 40 + lkf], pa1a, pa1b);
        cvt8store(&sW[0][lr * 40 + lkf],        &sW[1][lr * 40 + lkf],        pw0a, pw0b);
        __syncthreads();

        if (kt < 7) {   // prefetch next k-tile before compute
            const int k0 = (kt + 1) * 32;
            const float* pA0 = &A [(m0 +      lr) * EE + k0 + lkf];
            const float* pA1 = &A [(m0 + 64 + lr) * EE + k0 + lkf];
            const float* pW  = &Wm[(n0 +      lr) * EE + k0 + lkf];
            pa0a = *(const float4*)(pA0);     pa0b = *(const float4*)(pA0 + 4);
            pa1a = *(const float4*)(pA1);     pa1b = *(const float4*)(pA1 + 4);
            pw0a = *(const float4*)(pW);      pw0b = *(const float4*)(pW + 4);
        }

        #pragma unroll
        for (int ks = 0; ks < 2; ++ks) {
            unsigned ah[2][4], al[2][4], bh[4][2], bl[4][2];
            #pragma unroll
            for (int mt = 0; mt < 2; ++mt) {
                unsigned adr_h = (unsigned)__cvta_generic_to_shared(
                    &sA[0][(wm * 32 + mt * 16 + a_m) * 40 + ks * 16 + a_k]);
                unsigned adr_l = (unsigned)__cvta_generic_to_shared(
                    &sA[1][(wm * 32 + mt * 16 + a_m) * 40 + ks * 16 + a_k]);
                ldsm4(ah[mt], adr_h);
                ldsm4(al[mt], adr_l);
            }
            #pragma unroll
            for (int np = 0; np < 2; ++np) {
                unsigned t[4];
                unsigned adr_h = (unsigned)__cvta_generic_to_shared(
                    &sW[0][(wn * 32 + np * 16 + w_n) * 40 + ks * 16 + w_k]);
                ldsm4(t, adr_h);
                bh[np * 2][0] = t[0]; bh[np * 2][1] = t[1];
                bh[np * 2 + 1][0] = t[2]; bh[np * 2 + 1][1] = t[3];
                unsigned adr_l = (unsigned)__cvta_generic_to_shared(
                    &sW[1][(wn * 32 + np * 16 + w_n) * 40 + ks * 16 + w_k]);
                ldsm4(t, adr_l);
                bl[np * 2][0] = t[0]; bl[np * 2][1] = t[1];
                bl[np * 2 + 1][0] = t[2]; bl[np * 2 + 1][1] = t[3];
            }
            #pragma unroll
            for (int mt = 0; mt < 2; ++mt)
                #pragma unroll
                for (int nt = 0; nt < 4; ++nt) {
                    mma16816(acc[mt][nt], ah[mt], bh[nt]);   // hi*hi
                    mma16816(acc[mt][nt], ah[mt], bl[nt]);   // hi*lo
                    mma16816(acc[mt][nt], al[mt], bh[nt]);   // lo*hi
                }
        }
    }

    // epilogue: + bias, write fp32
    float* out = (z == 0) ? g_Q : (z == 1) ? g_K : g_V;
    const float* bias = (z == 0) ? bq : (z == 1) ? bk : bv;
    #pragma unroll
    for (int nt = 0; nt < 4; ++nt) {
        const int n = n0 + wn * 32 + nt * 8 + (lane & 3) * 2;
        const float b0 = bias[n], b1 = bias[n + 1];
        #pragma unroll
        for (int mt = 0; mt < 2; ++mt) {
            const int m = m0 + wm * 32 + mt * 16 + (lane >> 2);
            float2 r0 = make_float2(acc[mt][nt][0] + b0, acc[mt][nt][1] + b1);
            float2 r1 = make_float2(acc[mt][nt][2] + b0, acc[mt][nt][3] + b1);
            *(float2*)&out[m * EE + n] = r0;
            *(float2*)&out[(m + 8) * EE + n] = r1;
        }
    }
}

// ---------------------------------------------------------------------------
// Kernel 2: AFT-local attention. Per-channel softmax over a 65-wide window.
// Block: 256 thr, tile 64 rows x 64 channels; K/V smem tiles 128 rows
// (64 + 2S halo, zero-filled OOB). Each thread processes 8 CONSECUTIVE rows
// per pass (2 passes): each K/V smem value loaded once serves 8 windows.
// pos_bias[1..63] for the thread's channel in registers (w=0/64 -> p=1).
// Unshifted softmax (|log2 logits| << 80, no fp32 overflow possible).
// ---------------------------------------------------------------------------
template <bool CHECK>
__device__ __forceinline__ void aft_rows(
    int i0, int j0, int c, int bi, int e, int rg,
    const float* __restrict__ Ks, const float* __restrict__ Vs,
    const float* __restrict__ pb, float* __restrict__ out)
{
    #pragma unroll 1
    for (int pass = 0; pass < 2; ++pass) {
        const int il = pass * 32 + rg * 8;   // 8 consecutive rows il..il+7
        float qs[8], den[8], num[8];
        #pragma unroll
        for (int d = 0; d < 8; ++d) {
            const float qv = g_Q[(bi * LL + i0 + il + d) * EE + e];
            qs[d] = qv * LOG2E;
            float v0 = 1.0f, v64 = 1.0f;
            if (CHECK) {
                v0  = ((unsigned)(j0 + il + d)      < (unsigned)LL) ? 1.0f : 0.0f;
                v64 = ((unsigned)(j0 + il + d + 64) < (unsigned)LL) ? 1.0f : 0.0f;
            }
            den[d] = v0 + v64;                               // w=0, w=64: p = 1 (K masked to 0)
            num[d] = Vs[(il + d) * 64 + c] + Vs[(il + d + 64) * 64 + c];  // V zero-filled OOB
        }
        #pragma unroll
        for (int jo = 1; jo <= 70; ++jo) {
            const int r = (il + jo) * 64 + c;
            const float k = Ks[r];
            const float v = Vs[r];
            float vj = 1.0f;
            if (CHECK) vj = ((unsigned)(j0 + il + jo) < (unsigned)LL) ? 1.0f : 0.0f;
            #pragma unroll
            for (int d = 0; d < 8; ++d) {
                const int w = jo - d;        // compile-time
                if (w >= 1 && w <= 63) {
                    float l = qs[d] * (k + pb[w]);   // log2-domain logit
                    float p = ex2f(l);
                    if (CHECK) p *= vj;
                    den[d] += p;
                    num[d] = fmaf(p, v, num[d]);
                }
            }
        }
        #pragma unroll
        for (int d = 0; d < 8; ++d) {
            const float s = rcpf(1.0f + ex2f(-qs[d]));       // sigmoid(qv)
            out[(bi * LL + i0 + il + d) * EE + e] = s * s * num[d] * rcpf(den[d]);
        }
    }
}

__global__ __launch_bounds__(256, 2) void aft_local(
    const float* __restrict__ pos_bias,   // [65][256]
    float* __restrict__ out)              // [B][L][E]
{
    extern __shared__ float smem[];
    float* Ks = smem;                 // [128][64]
    float* Vs = smem + 128 * 64;      // [128][64]

    const int tid = threadIdx.x;
    const int c   = tid & 63;         // channel within block
    const int rg  = tid >> 6;         // row group 0..3 (uniform per warp)
    const int e0  = blockIdx.x * 64;
    const int i0  = blockIdx.y * 64;
    const int bi  = blockIdx.z;
    const int e   = e0 + c;
    const int j0  = i0 - 32;

    // Load K/V tile rows [i0-32, i0+95], zero-fill out-of-sequence rows.
    for (int idx = tid; idx < 128 * 16; idx += 256) {
        const int r  = idx >> 4;
        const int cc = (idx & 15) << 2;
        const int j  = j0 + r;
        float4 kv = make_float4(0.f, 0.f, 0.f, 0.f);
        float4 vv = make_float4(0.f, 0.f, 0.f, 0.f);
        if ((unsigned)j < (unsigned)LL) {
            const int off = (bi * LL + j) * EE + e0 + cc;
            kv = *(const float4*)&g_K[off];
            vv = *(const float4*)&g_V[off];
        }
        *(float4*)&Ks[r * 64 + cc] = kv;
        *(float4*)&Vs[r * 64 + cc] = vv;
    }

    // pos_bias column (w = 1..63 only; w=0/64 never read pb)
    float pb[64];
    #pragma unroll
    for (int w = 1; w < 64; ++w) pb[w] = pos_bias[w * EE + e];

    __syncthreads();

    const bool interior = (i0 >= 32) && (i0 + 96 <= LL);
    if (interior) aft_rows<false>(i0, j0, c, bi, e, rg, Ks, Vs, pb, out);
    else          aft_rows<true >(i0, j0, c, bi, e, rg, Ks, Vs, pb, out);
}

// ---------------------------------------------------------------------------
// launch
// ---------------------------------------------------------------------------
extern "C" void kernel_launch(void* const* d_in, const int* in_sizes, int n_in,
                              void* d_out, int out_size)
{
    const float* __restrict__ q  = (const float*)d_in[0];
    const float* __restrict__ Wq = (const float*)d_in[1];
    const float* __restrict__ bq = (const float*)d_in[2];
    const float* __restrict__ Wk = (const float*)d_in[3];
    const float* __restrict__ bk = (const float*)d_in[4];
    const float* __restrict__ Wv = (const float*)d_in[5];
    const float* __restrict__ bv = (const float*)d_in[6];
    const float* __restrict__ pb = (const float*)d_in[7];
    float* out = (float*)d_out;

    (void)in_sizes; (void)n_in; (void)out_size;

    // one-time attribute setup (idempotent, kept out of steady-state path)
    static bool s_init = false;
    if (!s_init) {
        cudaFuncSetAttribute(aft_local, cudaFuncAttributeMaxDynamicSharedMemorySize, 65536);
        s_init = true;
    }

    // 1: QKV projection on tensor cores (fp32->bf16 hi/lo split fused in-load)
    dim3 gg(32, 4, 3);
    qkv_mma<<<gg, 256>>>(q, Wq, Wk, Wv, bq, bk, bv);

    // 2: AFT local attention (64 KB dynamic smem)
    dim3 ga(EE / 64, LL / 64, BB);
    aft_local<<<ga, 256, 65536>>>(pb, out);
}

// round 8
// speedup vs baseline: 1.0560x; 1.0560x over previous
#include <cuda_runtime.h>
#include <cuda_bf16.h>

// Problem constants: B=4, L=1024, E=256, S=32, W=2S+1=65
#define BB 4
#define LL 1024
#define EE 256
#define LOG2E 1.4426950408889634f
#define PITCH 130   // transposed K/V smem pitch: conflict-free LDS.64 pairs

// Device-global scratch (no allocations allowed)
__device__ float g_Q[BB * LL * EE];
__device__ float g_K[BB * LL * EE];
__device__ float g_V[BB * LL * EE];

// ---------------------------------------------------------------------------
// helpers
// ---------------------------------------------------------------------------
__device__ __forceinline__ float ex2f(float x) {
    float r; asm("ex2.approx.f32 %0, %1;" : "=f"(r) : "f"(x)); return r;
}
__device__ __forceinline__ float rcpf(float x) {
    float r; asm("rcp.approx.f32 %0, %1;" : "=f"(r) : "f"(x)); return r;
}
__device__ __forceinline__ unsigned long long pack2s(float x) {
    unsigned long long r; unsigned u = __float_as_uint(x);
    asm("mov.b64 %0, {%1, %1};" : "=l"(r) : "r"(u)); return r;
}
__device__ __forceinline__ unsigned long long add2(unsigned long long a, unsigned long long b) {
    unsigned long long r; asm("add.rn.f32x2 %0, %1, %2;" : "=l"(r) : "l"(a), "l"(b)); return r;
}
__device__ __forceinline__ unsigned long long mul2(unsigned long long a, unsigned long long b) {
    unsigned long long r; asm("mul.rn.f32x2 %0, %1, %2;" : "=l"(r) : "l"(a), "l"(b)); return r;
}
__device__ __forceinline__ void unpk2(float& lo, float& hi, unsigned long long v) {
    unsigned a, b;
    asm("mov.b64 {%0, %1}, %2;" : "=r"(a), "=r"(b) : "l"(v));
    lo = __uint_as_float(a); hi = __uint_as_float(b);
}
__device__ __forceinline__ void ldsm4(unsigned* r, unsigned addr) {
    asm volatile("ldmatrix.sync.aligned.m8n8.x4.shared.b16 {%0,%1,%2,%3}, [%4];"
                 : "=r"(r[0]), "=r"(r[1]), "=r"(r[2]), "=r"(r[3]) : "r"(addr));
}
__device__ __forceinline__ void mma16816(float* c, const unsigned* a, const unsigned* b) {
    asm volatile(
        "mma.sync.aligned.m16n8k16.row.col.f32.bf16.bf16.f32 "
        "{%0,%1,%2,%3},{%4,%5,%6,%7},{%8,%9},{%0,%1,%2,%3};"
        : "+f"(c[0]), "+f"(c[1]), "+f"(c[2]), "+f"(c[3])
        : "r"(a[0]), "r"(a[1]), "r"(a[2]), "r"(a[3]), "r"(b[0]), "r"(b[1]));
}

// Convert 8 fp32 -> 8 bf16 hi + 8 bf16 lo (residual); store as uint4 pairs.
__device__ __forceinline__ void cvt8store(__nv_bfloat16* dh, __nv_bfloat16* dl,
                                          float4 a, float4 b) {
    float v[8] = {a.x, a.y, a.z, a.w, b.x, b.y, b.z, b.w};
    __nv_bfloat16 h[8], l[8];
    #pragma unroll
    for (int j = 0; j < 8; ++j) {
        h[j] = __float2bfloat16(v[j]);
        l[j] = __float2bfloat16(v[j] - __bfloat162float(h[j]));
    }
    *(uint4*)dh = *(uint4*)h;
    *(uint4*)dl = *(uint4*)l;
}

// ---------------------------------------------------------------------------
// Kernel 1: QKV projection via tensor cores (UNCHANGED — measured ~10.4us).
// fp32 -> bf16 hi/lo split fused into the load stage; 3-term split GEMM.
// ---------------------------------------------------------------------------
__global__ __launch_bounds__(256, 2) void qkv_mma(
    const float* __restrict__ A,
    const float* __restrict__ W0, const float* __restrict__ W1,
    const float* __restrict__ W2,
    const float* __restrict__ bq, const float* __restrict__ bk,
    const float* __restrict__ bv)
{
    __shared__ __align__(16) __nv_bfloat16 sA[2][128 * 40];
    __shared__ __align__(16) __nv_bfloat16 sW[2][64 * 40];

    const int tid = threadIdx.x;
    const int z  = blockIdx.z;
    const int m0 = blockIdx.x * 128;
    const int n0 = blockIdx.y * 64;
    const float* Wm = (z == 0) ? W0 : (z == 1) ? W1 : W2;

    const int lane = tid & 31, wid = tid >> 5;
    const int wm = wid & 3;
    const int wn = wid >> 2;
    const int lr  = tid >> 2;
    const int lkf = (tid & 3) * 8;

    float acc[2][4][4];
    #pragma unroll
    for (int mt = 0; mt < 2; ++mt)
        #pragma unroll
        for (int nt = 0; nt < 4; ++nt)
            #pragma unroll
            for (int r = 0; r < 4; ++r) acc[mt][nt][r] = 0.0f;

    const int mat = lane >> 3;
    const int a_m = (mat & 1) * 8 + (lane & 7);
    const int a_k = (mat >> 1) * 8;
    const int w_n = (mat >> 1) * 8 + (lane & 7);
    const int w_k = (mat & 1) * 8;

    float4 pa0a, pa0b, pa1a, pa1b, pw0a, pw0b;
    {
        const float* pA0 = &A [(m0 +      lr) * EE + lkf];
        const float* pA1 = &A [(m0 + 64 + lr) * EE + lkf];
        const float* pW  = &Wm[(n0 +      lr) * EE + lkf];
        pa0a = *(const float4*)(pA0);     pa0b = *(const float4*)(pA0 + 4);
        pa1a = *(const float4*)(pA1);     pa1b = *(const float4*)(pA1 + 4);
        pw0a = *(const float4*)(pW);      pw0b = *(const float4*)(pW + 4);
    }

    for (int kt = 0; kt < 8; ++kt) {
        __syncthreads();
        cvt8store(&sA[0][lr * 40 + lkf],        &sA[1][lr * 40 + lkf],        pa0a, pa0b);
        cvt8store(&sA[0][(64 + lr) * 40 + lkf], &sA[1][(64 + lr) * 40 + lkf], pa1a, pa1b);
        cvt8store(&sW[0][lr * 40 + lkf],        &sW[1][lr * 40 + lkf],        pw0a, pw0b);
        __syncthreads();

        if (kt < 7) {
            const int k0 = (kt + 1) * 32;
            const float* pA0 = &A [(m0 +      lr) * EE + k0 + lkf];
            const float* pA1 = &A [(m0 + 64 + lr) * EE + k0 + lkf];
            const float* pW  = &Wm[(n0 +      lr) * EE + k0 + lkf];
            pa0a = *(const float4*)(pA0);     pa0b = *(const float4*)(pA0 + 4);
            pa1a = *(const float4*)(pA1);     pa1b = *(const float4*)(pA1 + 4);
            pw0a = *(const float4*)(pW);      pw0b = *(const float4*)(pW + 4);
        }

        #pragma unroll
        for (int ks = 0; ks < 2; ++ks) {
            unsigned ah[2][4], al[2][4], bh[4][2], bl[4][2];
            #pragma unroll
            for (int mt = 0; mt < 2; ++mt) {
                unsigned adr_h = (unsigned)__cvta_generic_to_shared(
                    &sA[0][(wm * 32 + mt * 16 + a_m) * 40 + ks * 16 + a_k]);
                unsigned adr_l = (unsigned)__cvta_generic_to_shared(
                    &sA[1][(wm * 32 + mt * 16 + a_m) * 40 + ks * 16 + a_k]);
                ldsm4(ah[mt], adr_h);
                ldsm4(al[mt], adr_l);
            }
            #pragma unroll
            for (int np = 0; np < 2; ++np) {
                unsigned t[4];
                unsigned adr_h = (unsigned)__cvta_generic_to_shared(
                    &sW[0][(wn * 32 + np * 16 + w_n) * 40 + ks * 16 + w_k]);
                ldsm4(t, adr_h);
                bh[np * 2][0] = t[0]; bh[np * 2][1] = t[1];
                bh[np * 2 + 1][0] = t[2]; bh[np * 2 + 1][1] = t[3];
                unsigned adr_l = (unsigned)__cvta_generic_to_shared(
                    &sW[1][(wn * 32 + np * 16 + w_n) * 40 + ks * 16 + w_k]);
                ldsm4(t, adr_l);
                bl[np * 2][0] = t[0]; bl[np * 2][1] = t[1];
                bl[np * 2 + 1][0] = t[2]; bl[np * 2 + 1][1] = t[3];
            }
            #pragma unroll
            for (int mt = 0; mt < 2; ++mt)
                #pragma unroll
                for (int nt = 0; nt < 4; ++nt) {
                    mma16816(acc[mt][nt], ah[mt], bh[nt]);
                    mma16816(acc[mt][nt], ah[mt], bl[nt]);
                    mma16816(acc[mt][nt], al[mt], bh[nt]);
                }
        }
    }

    float* out = (z == 0) ? g_Q : (z == 1) ? g_K : g_V;
    const float* bias = (z == 0) ? bq : (z == 1) ? bk : bv;
    #pragma unroll
    for (int nt = 0; nt < 4; ++nt) {
        const int n = n0 + wn * 32 + nt * 8 + (lane & 3) * 2;
        const float b0 = bias[n], b1 = bias[n + 1];
        #pragma unroll
        for (int mt = 0; mt < 2; ++mt) {
            const int m = m0 + wm * 32 + mt * 16 + (lane >> 2);
            float2 r0 = make_float2(acc[mt][nt][0] + b0, acc[mt][nt][1] + b1);
            float2 r1 = make_float2(acc[mt][nt][2] + b0, acc[mt][nt][3] + b1);
            *(float2*)&out[m * EE + n] = r0;
            *(float2*)&out[(m + 8) * EE + n] = r1;
        }
    }
}

// ---------------------------------------------------------------------------
// Kernel 2: AFT-local attention, packed-f32x2 rewrite.
// Tile: 64 rows x 64 channels, 256 thr; thread rows il = 4*rt + rg (rt 0..15)
// => il parity FIXED per thread => window pairs align to one parity =>
// pos_bias pairs live in 31 register float2's; K/V transposed in smem
// (pitch 130, conflict-free LDS.64) so each pair costs one 64-bit load.
// Per 2 windows: 2x LDS.64 + add.f32x2 + mul.f32x2 + 2x ex2 + 2 FADD + 2 FFMA.
// Rolled row loop (code ~6KB); unshifted softmax (no overflow possible).
// ---------------------------------------------------------------------------
template <bool CHECK>
__device__ __forceinline__ void aft_row(
    int il, int j0, int i0, int c, int bi, int e,
    const float* __restrict__ Kt, const float* __restrict__ Vt,
    const float2* __restrict__ pb2, float pbl, int w0, int wl,
    unsigned long long /*unused*/, float* __restrict__ out)
{
    const float qv = g_Q[(bi * LL + i0 + il) * EE + e];
    const float qs = qv * LOG2E;
    const unsigned long long qs2 = pack2s(qs);

    // boundary windows w=0 (r=il) and w=64 (r=il+64): K masked -> p = valid?1:0
    float den, num;
    {
        float vA = 1.0f, vB = 1.0f;
        if (CHECK) {
            vA = ((unsigned)(j0 + il)      < (unsigned)LL) ? 1.0f : 0.0f;
            vB = ((unsigned)(j0 + il + 64) < (unsigned)LL) ? 1.0f : 0.0f;
        }
        den = vA + vB;
        num = Vt[c * PITCH + il] + Vt[c * PITCH + il + 64];   // zero-filled OOB
    }
    // leftover scalar window wl
    {
        const int r = il + wl;
        float l = qs * (Kt[c * PITCH + r] + pbl);
        float p = ex2f(l);
        if (CHECK) p *= ((unsigned)(j0 + r) < (unsigned)LL) ? 1.0f : 0.0f;
        den += p;
        num = fmaf(p, Vt[c * PITCH + r], num);
    }
    // 31 packed pairs covering the remaining windows
    const float* kp = &Kt[c * PITCH + il + w0];
    const float* vp = &Vt[c * PITCH + il + w0];
    #pragma unroll
    for (int t = 0; t < 31; ++t) {
        float2 k2 = *(const float2*)(kp + 2 * t);      // LDS.64, 8B-aligned
        float2 v2 = *(const float2*)(vp + 2 * t);
        unsigned long long kk = *(const unsigned long long*)&k2;
        unsigned long long bb = *(const unsigned long long*)&pb2[t];
        unsigned long long l2 = mul2(add2(kk, bb), qs2);
        float l0, l1; unpk2(l0, l1, l2);
        float p0 = ex2f(l0), p1 = ex2f(l1);
        if (CHECK) {
            p0 *= ((unsigned)(j0 + il + w0 + 2 * t)     < (unsigned)LL) ? 1.0f : 0.0f;
            p1 *= ((unsigned)(j0 + il + w0 + 2 * t + 1) < (unsigned)LL) ? 1.0f : 0.0f;
        }
        den += p0; den += p1;
        num = fmaf(p0, v2.x, num);
        num = fmaf(p1, v2.y, num);
    }
    const float s = rcpf(1.0f + ex2f(-qs));            // sigmoid(qv)
    out[(bi * LL + i0 + il) * EE + e] = s * s * num * rcpf(den);
}

__global__ __launch_bounds__(256, 2) void aft_local(
    const float* __restrict__ pos_bias,   // [65][256]
    float* __restrict__ out)              // [B][L][E]
{
    extern __shared__ float smem[];
    float* Kt = smem;                  // [64 ch][PITCH rows]
    float* Vt = smem + 64 * PITCH;

    const int tid = threadIdx.x;
    const int c   = tid & 63;          // channel within block
    const int rg  = tid >> 6;          // row group 0..3 (uniform per warp)
    const int e0  = blockIdx.x * 64;
    const int i0  = blockIdx.y * 64;
    const int bi  = blockIdx.z;
    const int e   = e0 + c;
    const int j0  = i0 - 32;

    // Fill transposed K/V tiles: rows r=0..127 (j = j0+r), zero-fill OOB.
    for (int idx = tid; idx < 128 * 16; idx += 256) {
        const int r  = idx >> 4;
        const int cc = (idx & 15) << 2;
        const int j  = j0 + r;
        float4 kv = make_float4(0.f, 0.f, 0.f, 0.f);
        float4 vv = make_float4(0.f, 0.f, 0.f, 0.f);
        if ((unsigned)j < (unsigned)LL) {
            const int off = (bi * LL + j) * EE + e0 + cc;
            kv = *(const float4*)&g_K[off];
            vv = *(const float4*)&g_V[off];
        }
        Kt[(cc + 0) * PITCH + r] = kv.x;  Kt[(cc + 1) * PITCH + r] = kv.y;
        Kt[(cc + 2) * PITCH + r] = kv.z;  Kt[(cc + 3) * PITCH + r] = kv.w;
        Vt[(cc + 0) * PITCH + r] = vv.x;  Vt[(cc + 1) * PITCH + r] = vv.y;
        Vt[(cc + 2) * PITCH + r] = vv.z;  Vt[(cc + 3) * PITCH + r] = vv.w;
    }

    // Parity-fixed pos_bias pairs. il = 4*rt + rg -> parity(il) = rg&1.
    // even il: pairs w=2..63 (w0=2), leftover w=1
    // odd  il: pairs w=1..62 (w0=1), leftover w=63
    const int par = rg & 1;
    const int w0  = 2 - par;
    const int wl  = par ? 63 : 1;
    float2 pb2[31];
    #pragma unroll
    for (int t = 0; t < 31; ++t) {
        const int w = w0 + 2 * t;
        pb2[t].x = pos_bias[w * EE + e];
        pb2[t].y = pos_bias[(w + 1) * EE + e];
    }
    const float pbl = pos_bias[wl * EE + e];

    __syncthreads();

    const bool interior = (i0 >= 32) && (i0 + 96 <= LL);
    if (interior) {
        #pragma unroll 1
        for (int rt = 0; rt < 16; ++rt)
            aft_row<false>(rt * 4 + rg, j0, i0, c, bi, e, Kt, Vt, pb2, pbl, w0, wl, 0ull, out);
    } else {
        #pragma unroll 1
        for (int rt = 0; rt < 16; ++rt)
            aft_row<true >(rt * 4 + rg, j0, i0, c, bi, e, Kt, Vt, pb2, pbl, w0, wl, 0ull, out);
    }
}

// ---------------------------------------------------------------------------
// launch
// ---------------------------------------------------------------------------
extern "C" void kernel_launch(void* const* d_in, const int* in_sizes, int n_in,
                              void* d_out, int out_size)
{
    const float* q  = (const float*)d_in[0];
    const float* Wq = (const float*)d_in[1];
    const float* bq = (const float*)d_in[2];
    const float* Wk = (const float*)d_in[3];
    const float* bk = (const float*)d_in[4];
    const float* Wv = (const float*)d_in[5];
    const float* bv = (const float*)d_in[6];
    const float* pb = (const float*)d_in[7];
    float* out = (float*)d_out;

    (void)in_sizes; (void)n_in; (void)out_size;

    static bool s_init = false;
    if (!s_init) {
        cudaFuncSetAttribute(aft_local, cudaFuncAttributeMaxDynamicSharedMemorySize,
                             2 * 64 * PITCH * 4);
        s_init = true;
    }

    // 1: QKV projection on tensor cores (fp32->bf16 hi/lo split fused in-load)
    dim3 gg(32, 4, 3);
    qkv_mma<<<gg, 256>>>(q, Wq, Wk, Wv, bq, bk, bv);

    // 2: AFT local attention (transposed-smem packed-f32x2 version)
    dim3 ga(EE / 64, LL / 64, BB);
    aft_local<<<ga, 256, 2 * 64 * PITCH * 4>>>(pb, out);
}

// round 10
// speedup vs baseline: 1.1020x; 1.0436x over previous
#include <cuda_runtime.h>
#include <cuda_bf16.h>

// Problem constants: B=4, L=1024, E=256, S=32, W=2S+1=65
#define BB 4
#define LL 1024
#define EE 256
#define LOG2E 1.4426950408889634f
#define PITCH 130   // transposed K/V smem pitch (even -> 8B-aligned LDS.64 pairs)

// Device-global scratch (no allocations allowed)
__device__ float g_Q[BB * LL * EE];
__device__ float g_K[BB * LL * EE];
__device__ float g_V[BB * LL * EE];

// ---------------------------------------------------------------------------
// helpers
// ---------------------------------------------------------------------------
__device__ __forceinline__ float ex2f(float x) {
    float r; asm("ex2.approx.f32 %0, %1;" : "=f"(r) : "f"(x)); return r;
}
__device__ __forceinline__ float rcpf(float x) {
    float r; asm("rcp.approx.f32 %0, %1;" : "=f"(r) : "f"(x)); return r;
}
__device__ __forceinline__ unsigned long long pack2s(float x) {
    unsigned long long r; unsigned u = __float_as_uint(x);
    asm("mov.b64 %0, {%1, %1};" : "=l"(r) : "r"(u)); return r;
}
__device__ __forceinline__ unsigned long long add2(unsigned long long a, unsigned long long b) {
    unsigned long long r; asm("add.rn.f32x2 %0, %1, %2;" : "=l"(r) : "l"(a), "l"(b)); return r;
}
__device__ __forceinline__ unsigned long long mul2(unsigned long long a, unsigned long long b) {
    unsigned long long r; asm("mul.rn.f32x2 %0, %1, %2;" : "=l"(r) : "l"(a), "l"(b)); return r;
}
__device__ __forceinline__ void unpk2(float& lo, float& hi, unsigned long long v) {
    unsigned a, b;
    asm("mov.b64 {%0, %1}, %2;" : "=r"(a), "=r"(b) : "l"(v));
    lo = __uint_as_float(a); hi = __uint_as_float(b);
}
__device__ __forceinline__ float inbf(int j) {
    return ((unsigned)j < (unsigned)LL) ? 1.0f : 0.0f;
}
__device__ __forceinline__ void ldsm4(unsigned* r, unsigned addr) {
    asm volatile("ldmatrix.sync.aligned.m8n8.x4.shared.b16 {%0,%1,%2,%3}, [%4];"
                 : "=r"(r[0]), "=r"(r[1]), "=r"(r[2]), "=r"(r[3]) : "r"(addr));
}
__device__ __forceinline__ void mma16816(float* c, const unsigned* a, const unsigned* b) {
    asm volatile(
        "mma.sync.aligned.m16n8k16.row.col.f32.bf16.bf16.f32 "
        "{%0,%1,%2,%3},{%4,%5,%6,%7},{%8,%9},{%0,%1,%2,%3};"
        : "+f"(c[0]), "+f"(c[1]), "+f"(c[2]), "+f"(c[3])
        : "r"(a[0]), "r"(a[1]), "r"(a[2]), "r"(a[3]), "r"(b[0]), "r"(b[1]));
}

// Convert 8 fp32 -> 8 bf16 hi + 8 bf16 lo (residual); store as uint4 pairs.
__device__ __forceinline__ void cvt8store(__nv_bfloat16* dh, __nv_bfloat16* dl,
                                          float4 a, float4 b) {
    float v[8] = {a.x, a.y, a.z, a.w, b.x, b.y, b.z, b.w};
    __nv_bfloat16 h[8], l[8];
    #pragma unroll
    for (int j = 0; j < 8; ++j) {
        h[j] = __float2bfloat16(v[j]);
        l[j] = __float2bfloat16(v[j] - __bfloat162float(h[j]));
    }
    *(uint4*)dh = *(uint4*)h;
    *(uint4*)dl = *(uint4*)l;
}

// ---------------------------------------------------------------------------
// Kernel 1: QKV projection via tensor cores (FROZEN — measured ~10.4us).
// ---------------------------------------------------------------------------
__global__ __launch_bounds__(256, 2) void qkv_mma(
    const float* __restrict__ A,
    const float* __restrict__ W0, const float* __restrict__ W1,
    const float* __restrict__ W2,
    const float* __restrict__ bq, const float* __restrict__ bk,
    const float* __restrict__ bv)
{
    __shared__ __align__(16) __nv_bfloat16 sA[2][128 * 40];
    __shared__ __align__(16) __nv_bfloat16 sW[2][64 * 40];

    const int tid = threadIdx.x;
    const int z  = blockIdx.z;
    const int m0 = blockIdx.x * 128;
    const int n0 = blockIdx.y * 64;
    const float* Wm = (z == 0) ? W0 : (z == 1) ? W1 : W2;

    const int lane = tid & 31, wid = tid >> 5;
    const int wm = wid & 3;
    const int wn = wid >> 2;
    const int lr  = tid >> 2;
    const int lkf = (tid & 3) * 8;

    float acc[2][4][4];
    #pragma unroll
    for (int mt = 0; mt < 2; ++mt)
        #pragma unroll
        for (int nt = 0; nt < 4; ++nt)
            #pragma unroll
            for (int r = 0; r < 4; ++r) acc[mt][nt][r] = 0.0f;

    const int mat = lane >> 3;
    const int a_m = (mat & 1) * 8 + (lane & 7);
    const int a_k = (mat >> 1) * 8;
    const int w_n = (mat >> 1) * 8 + (lane & 7);
    const int w_k = (mat & 1) * 8;

    float4 pa0a, pa0b, pa1a, pa1b, pw0a, pw0b;
    {
        const float* pA0 = &A [(m0 +      lr) * EE + lkf];
        const float* pA1 = &A [(m0 + 64 + lr) * EE + lkf];
        const float* pW  = &Wm[(n0 +      lr) * EE + lkf];
        pa0a = *(const float4*)(pA0);     pa0b = *(const float4*)(pA0 + 4);
        pa1a = *(const float4*)(pA1);     pa1b = *(const float4*)(pA1 + 4);
        pw0a = *(const float4*)(pW);      pw0b = *(const float4*)(pW + 4);
    }

    for (int kt = 0; kt < 8; ++kt) {
        __syncthreads();
        cvt8store(&sA[0][lr * 40 + lkf],        &sA[1][lr * 40 + lkf],        pa0a, pa0b);
        cvt8store(&sA[0][(64 + lr) * 40 + lkf], &sA[1][(64 + lr) * 40 + lkf], pa1a, pa1b);
        cvt8store(&sW[0][lr * 40 + lkf],        &sW[1][lr * 40 + lkf],        pw0a, pw0b);
        __syncthreads();

        if (kt < 7) {
            const int k0 = (kt + 1) * 32;
            const float* pA0 = &A [(m0 +      lr) * EE + k0 + lkf];
            const float* pA1 = &A [(m0 + 64 + lr) * EE + k0 + lkf];
            const float* pW  = &Wm[(n0 +      lr) * EE + k0 + lkf];
            pa0a = *(const float4*)(pA0);     pa0b = *(const float4*)(pA0 + 4);
            pa1a = *(const float4*)(pA1);     pa1b = *(const float4*)(pA1 + 4);
            pw0a = *(const float4*)(pW);      pw0b = *(const float4*)(pW + 4);
        }

        #pragma unroll
        for (int ks = 0; ks < 2; ++ks) {
            unsigned ah[2][4], al[2][4], bh[4][2], bl[4][2];
            #pragma unroll
            for (int mt = 0; mt < 2; ++mt) {
                unsigned adr_h = (unsigned)__cvta_generic_to_shared(
                    &sA[0][(wm * 32 + mt * 16 + a_m) * 40 + ks * 16 + a_k]);
                unsigned adr_l = (unsigned)__cvta_generic_to_shared(
                    &sA[1][(wm * 32 + mt * 16 + a_m) * 40 + ks * 16 + a_k]);
                ldsm4(ah[mt], adr_h);
                ldsm4(al[mt], adr_l);
            }
            #pragma unroll
            for (int np = 0; np < 2; ++np) {
                unsigned t[4];
                unsigned adr_h = (unsigned)__cvta_generic_to_shared(
                    &sW[0][(wn * 32 + np * 16 + w_n) * 40 + ks * 16 + w_k]);
                ldsm4(t, adr_h);
                bh[np * 2][0] = t[0]; bh[np * 2][1] = t[1];
                bh[np * 2 + 1][0] = t[2]; bh[np * 2 + 1][1] = t[3];
                unsigned adr_l = (unsigned)__cvta_generic_to_shared(
                    &sW[1][(wn * 32 + np * 16 + w_n) * 40 + ks * 16 + w_k]);
                ldsm4(t, adr_l);
                bl[np * 2][0] = t[0]; bl[np * 2][1] = t[1];
                bl[np * 2 + 1][0] = t[2]; bl[np * 2 + 1][1] = t[3];
            }
            #pragma unroll
            for (int mt = 0; mt < 2; ++mt)
                #pragma unroll
                for (int nt = 0; nt < 4; ++nt) {
                    mma16816(acc[mt][nt], ah[mt], bh[nt]);
                    mma16816(acc[mt][nt], ah[mt], bl[nt]);
                    mma16816(acc[mt][nt], al[mt], bh[nt]);
                }
        }
    }

    float* out = (z == 0) ? g_Q : (z == 1) ? g_K : g_V;
    const float* bias = (z == 0) ? bq : (z == 1) ? bk : bv;
    #pragma unroll
    for (int nt = 0; nt < 4; ++nt) {
        const int n = n0 + wn * 32 + nt * 8 + (lane & 3) * 2;
        const float b0 = bias[n], b1 = bias[n + 1];
        #pragma unroll
        for (int mt = 0; mt < 2; ++mt) {
            const int m = m0 + wm * 32 + mt * 16 + (lane >> 2);
            float2 r0 = make_float2(acc[mt][nt][0] + b0, acc[mt][nt][1] + b1);
            float2 r1 = make_float2(acc[mt][nt][2] + b0, acc[mt][nt][3] + b1);
            *(float2*)&out[m * EE + n] = r0;
            *(float2*)&out[(m + 8) * EE + n] = r1;
        }
    }
}

// ---------------------------------------------------------------------------
// Kernel 2: AFT-local attention — same-parity 2-row pairing (il, il+2).
// Rows il and il+2 (same parity) share every K/V pair load AND the same
// pos_bias pair array: pbp[u] serves row A at index t, row C at index t-1.
// Per tile-row pair t: 2x LDS.64 serve FOUR window evals (4 B/window).
// Lane-partial edge pairs resolve at compile time in the unrolled t loop.
// MUFU (1 ex2/window) is the intended binding floor (~28K cyc/SMSP).
// ---------------------------------------------------------------------------
template <int PAR, bool CHECK>
__device__ __forceinline__ void pair2(
    const int il, const int j0, const int i0, const int cb, const int bi,
    const int e,
    const float* __restrict__ Kt, const float* __restrict__ Vt,
    const float2* __restrict__ pbp, const float px,
    float* __restrict__ out)
{
    const int A = il, C = il + 2;
    const float qA = g_Q[(bi * LL + i0 + A) * EE + e] * LOG2E;
    const float qC = g_Q[(bi * LL + i0 + C) * EE + e] * LOG2E;
    const unsigned long long qA2 = pack2s(qA), qC2 = pack2s(qC);

    // boundary windows w=0 / w=64: K masked to 0 -> p = valid ? 1 : 0
    float denA, numA, denC, numC;
    {
        float vA0 = 1.f, vA6 = 1.f, vC0 = 1.f, vC6 = 1.f;
        if (CHECK) {
            vA0 = inbf(j0 + A);  vA6 = inbf(j0 + A + 64);
            vC0 = inbf(j0 + C);  vC6 = inbf(j0 + C + 64);
        }
        denA = vA0 + vA6;  numA = Vt[cb + A] + Vt[cb + A + 64];
        denC = vC0 + vC6;  numC = Vt[cb + C] + Vt[cb + C + 64];
    }

    const int rbase = il + 2 - PAR;          // even for both parities
    if (PAR == 0) {                          // A's w=1 (r=il+1) not in any pair
        const float k = Kt[cb + il + 1], v = Vt[cb + il + 1];
        float p = ex2f(qA * (k + px));       // px = pb[1]
        if (CHECK) p *= inbf(j0 + il + 1);
        denA += p; numA = fmaf(p, v, numA);
    }

    constexpr int T = 32 + PAR;
    #pragma unroll
    for (int t = 0; t < T; ++t) {
        const int r = rbase + 2 * t;
        const float2 k2 = *(const float2*)&Kt[cb + r];   // LDS.64, 8B-aligned
        const float2 v2 = *(const float2*)&Vt[cb + r];
        const unsigned long long k2u = *(const unsigned long long*)&k2;
        float m0 = 1.f, m1 = 1.f;
        if (CHECK) { m0 = inbf(j0 + r); m1 = inbf(j0 + r + 1); }

        const int wA0 = 2 - PAR + 2 * t;     // folds per unrolled iteration
        if (wA0 >= 1 && wA0 + 1 <= 63) {     // full pair for row A -> pbp[t]
            unsigned long long l2 =
                mul2(add2(k2u, *(const unsigned long long*)&pbp[t]), qA2);
            float l0, l1; unpk2(l0, l1, l2);
            float p0 = ex2f(l0), p1 = ex2f(l1);
            if (CHECK) { p0 *= m0; p1 *= m1; }
            denA += p0; denA += p1;
            numA = fmaf(p0, v2.x, numA);
            numA = fmaf(p1, v2.y, numA);
        } else if (wA0 == 63) {              // PAR=1, t=31: lane0 only (w=63)
            float p = ex2f(qA * (k2.x + px));    // px = pb[63]
            if (CHECK) p *= m0;
            denA += p; numA = fmaf(p, v2.x, numA);
        }

        const int wC0 = wA0 - 2;
        if (wC0 >= 1 && wC0 + 1 <= 63) {     // full pair for row C -> pbp[t-1]
            unsigned long long l2 =
                mul2(add2(k2u, *(const unsigned long long*)&pbp[t - 1]), qC2);
            float l0, l1; unpk2(l0, l1, l2);
            float p0 = ex2f(l0), p1 = ex2f(l1);
            if (CHECK) { p0 *= m0; p1 *= m1; }
            denC += p0; denC += p1;
            numC = fmaf(p0, v2.x, numC);
            numC = fmaf(p1, v2.y, numC);
        } else if (wC0 == 0) {               // PAR=0, t=0: lane1 only (w'=1)
            float p = ex2f(qC * (k2.y + px));    // px = pb[1]
            if (CHECK) p *= m1;
            denC += p; numC = fmaf(p, v2.y, numC);
        } else if (wC0 == 63) {              // PAR=1, t=32: lane0 only (w'=63)
            float p = ex2f(qC * (k2.x + px));    // px = pb[63]
            if (CHECK) p *= m0;
            denC += p; numC = fmaf(p, v2.x, numC);
        }
    }

    const float sA = rcpf(1.0f + ex2f(-qA)); // sigmoid(Q) (qA already *log2e)
    const float sC = rcpf(1.0f + ex2f(-qC));
    out[(bi * LL + i0 + A) * EE + e] = sA * sA * numA * rcpf(denA);
    out[(bi * LL + i0 + C) * EE + e] = sC * sC * numC * rcpf(denC);
}

__global__ __launch_bounds__(256, 2) void aft_local(
    const float* __restrict__ pos_bias,   // [65][256]
    float* __restrict__ out)              // [B][L][E]
{
    extern __shared__ float smem[];
    float* Kt = smem;                  // [64 ch][PITCH rows]
    float* Vt = smem + 64 * PITCH;

    const int tid = threadIdx.x;
    const int c   = tid & 63;          // channel within block
    const int rg  = tid >> 6;          // 0..3, uniform per warp
    const int s   = rg & 1;            // row parity (PAR)
    const int gh  = rg >> 1;
    const int e0  = blockIdx.x * 64;
    const int i0  = blockIdx.y * 64;
    const int bi  = blockIdx.z;
    const int e   = e0 + c;
    const int j0  = i0 - 32;
    const int cb  = c * PITCH;

    // Fill transposed K/V tiles: rows r=0..127 (j = j0+r), zero-fill OOB.
    for (int idx = tid; idx < 128 * 16; idx += 256) {
        const int r  = idx >> 4;
        const int cc = (idx & 15) << 2;
        const int j  = j0 + r;
        float4 kv = make_float4(0.f, 0.f, 0.f, 0.f);
        float4 vv = make_float4(0.f, 0.f, 0.f, 0.f);
        if ((unsigned)j < (unsigned)LL) {
            const int off = (bi * LL + j) * EE + e0 + cc;
            kv = *(const float4*)&g_K[off];
            vv = *(const float4*)&g_V[off];
        }
        Kt[(cc + 0) * PITCH + r] = kv.x;  Kt[(cc + 1) * PITCH + r] = kv.y;
        Kt[(cc + 2) * PITCH + r] = kv.z;  Kt[(cc + 3) * PITCH + r] = kv.w;
        Vt[(cc + 0) * PITCH + r] = vv.x;  Vt[(cc + 1) * PITCH + r] = vv.y;
        Vt[(cc + 2) * PITCH + r] = vv.z;  Vt[(cc + 3) * PITCH + r] = vv.w;
    }

    // Parity-fixed pos_bias pairs: pbp[u] = {pb[w0+2u], pb[w0+2u+1]},
    // w0 = 2-s -> covers pb[2..63] (s=0) or pb[1..62] (s=1); px = leftover.
    const int w0p = 2 - s;
    float2 pbp[31];
    #pragma unroll
    for (int u = 0; u < 31; ++u) {
        const int w = w0p + 2 * u;
        pbp[u].x = pos_bias[w * EE + e];
        pbp[u].y = pos_bias[(w + 1) * EE + e];
    }
    const float px = pos_bias[(s ? 63 : 1) * EE + e];

    __syncthreads();

    const bool interior = (i0 >= 32) && (i0 + 96 <= LL);
    if (interior) {
        if (s == 0) {
            #pragma unroll 1
            for (int rt = 0; rt < 8; ++rt)
                pair2<0, false>(8 * rt + 4 * gh, j0, i0, cb, bi, e, Kt, Vt, pbp, px, out);
        } else {
            #pragma unroll 1
            for (int rt = 0; rt < 8; ++rt)
                pair2<1, false>(8 * rt + 4 * gh + 1, j0, i0, cb, bi, e, Kt, Vt, pbp, px, out);
        }
    } else {
        if (s == 0) {
            #pragma unroll 1
            for (int rt = 0; rt < 8; ++rt)
                pair2<0, true>(8 * rt + 4 * gh, j0, i0, cb, bi, e, Kt, Vt, pbp, px, out);
        } else {
            #pragma unroll 1
            for (int rt = 0; rt < 8; ++rt)
                pair2<1, true>(8 * rt + 4 * gh + 1, j0, i0, cb, bi, e, Kt, Vt, pbp, px, out);
        }
    }
}

// ---------------------------------------------------------------------------
// launch
// ---------------------------------------------------------------------------
extern "C" void kernel_launch(void* const* d_in, const int* in_sizes, int n_in,
                              void* d_out, int out_size)
{
    const float* q  = (const float*)d_in[0];
    const float* Wq = (const float*)d_in[1];
    const float* bq = (const float*)d_in[2];
    const float* Wk = (const float*)d_in[3];
    const float* bk = (const float*)d_in[4];
    const float* Wv = (const float*)d_in[5];
    const float* bv = (const float*)d_in[6];
    const float* pb = (const float*)d_in[7];
    float* out = (float*)d_out;

    (void)in_sizes; (void)n_in; (void)out_size;

    static bool s_init = false;
    if (!s_init) {
        cudaFuncSetAttribute(aft_local, cudaFuncAttributeMaxDynamicSharedMemorySize,
                             2 * 64 * PITCH * 4);
        s_init = true;
    }

    // 1: QKV projection on tensor cores (fp32->bf16 hi/lo split fused in-load)
    dim3 gg(32, 4, 3);
    qkv_mma<<<gg, 256>>>(q, Wq, Wk, Wv, bq, bk, bv);

    // 2: AFT local attention (2-row-paired packed-f32x2 version)
    dim3 ga(EE / 64, LL / 64, BB);
    aft_local<<<ga, 256, 2 * 64 * PITCH * 4>>>(pb, out);
}

// round 12
// speedup vs baseline: 1.1033x; 1.0011x over previous
#include <cuda_runtime.h>
#include <cuda_bf16.h>

// Problem constants: B=4, L=1024, E=256, S=32, W=2S+1=65
#define BB 4
#define LL 1024
#define EE 256
#define LOG2E 1.4426950408889634f
#define PITCH2 130   // K/V transposed pitch (520B lane stride -> conflict-free LDS.64)
#define PBPITCH 67   // pos_bias smem pitch (3c mod 32 bijective -> conflict-free LDS.32)

// Device-global scratch (no allocations allowed)
__device__ float g_Q[BB * LL * EE];
__device__ float g_K[BB * LL * EE];
__device__ float g_V[BB * LL * EE];

// ---------------------------------------------------------------------------
// helpers
// ---------------------------------------------------------------------------
__device__ __forceinline__ float ex2f(float x) {
    float r; asm("ex2.approx.f32 %0, %1;" : "=f"(r) : "f"(x)); return r;
}
__device__ __forceinline__ float rcpf(float x) {
    float r; asm("rcp.approx.f32 %0, %1;" : "=f"(r) : "f"(x)); return r;
}
__device__ __forceinline__ float inbf(int j) {
    return ((unsigned)j < (unsigned)LL) ? 1.0f : 0.0f;
}
__device__ __forceinline__ void ldsm4(unsigned* r, unsigned addr) {
    asm volatile("ldmatrix.sync.aligned.m8n8.x4.shared.b16 {%0,%1,%2,%3}, [%4];"
                 : "=r"(r[0]), "=r"(r[1]), "=r"(r[2]), "=r"(r[3]) : "r"(addr));
}
__device__ __forceinline__ void mma16816(float* c, const unsigned* a, const unsigned* b) {
    asm volatile(
        "mma.sync.aligned.m16n8k16.row.col.f32.bf16.bf16.f32 "
        "{%0,%1,%2,%3},{%4,%5,%6,%7},{%8,%9},{%0,%1,%2,%3};"
        : "+f"(c[0]), "+f"(c[1]), "+f"(c[2]), "+f"(c[3])
        : "r"(a[0]), "r"(a[1]), "r"(a[2]), "r"(a[3]), "r"(b[0]), "r"(b[1]));
}

// Convert 8 fp32 -> 8 bf16 hi + 8 bf16 lo (residual); store as uint4 pairs.
__device__ __forceinline__ void cvt8store(__nv_bfloat16* dh, __nv_bfloat16* dl,
                                          float4 a, float4 b) {
    float v[8] = {a.x, a.y, a.z, a.w, b.x, b.y, b.z, b.w};
    __nv_bfloat16 h[8], l[8];
    #pragma unroll
    for (int j = 0; j < 8; ++j) {
        h[j] = __float2bfloat16(v[j]);
        l[j] = __float2bfloat16(v[j] - __bfloat162float(h[j]));
    }
    *(uint4*)dh = *(uint4*)h;
    *(uint4*)dl = *(uint4*)l;
}

// ---------------------------------------------------------------------------
// Kernel 1: QKV projection via tensor cores (FROZEN — measured ~10.4us).
// ---------------------------------------------------------------------------
__global__ __launch_bounds__(256, 2) void qkv_mma(
    const float* __restrict__ A,
    const float* __restrict__ W0, const float* __restrict__ W1,
    const float* __restrict__ W2,
    const float* __restrict__ bq, const float* __restrict__ bk,
    const float* __restrict__ bv)
{
    __shared__ __align__(16) __nv_bfloat16 sA[2][128 * 40];
    __shared__ __align__(16) __nv_bfloat16 sW[2][64 * 40];

    const int tid = threadIdx.x;
    const int z  = blockIdx.z;
    const int m0 = blockIdx.x * 128;
    const int n0 = blockIdx.y * 64;
    const float* Wm = (z == 0) ? W0 : (z == 1) ? W1 : W2;

    const int lane = tid & 31, wid = tid >> 5;
    const int wm = wid & 3;
    const int wn = wid >> 2;
    const int lr  = tid >> 2;
    const int lkf = (tid & 3) * 8;

    float acc[2][4][4];
    #pragma unroll
    for (int mt = 0; mt < 2; ++mt)
        #pragma unroll
        for (int nt = 0; nt < 4; ++nt)
            #pragma unroll
            for (int r = 0; r < 4; ++r) acc[mt][nt][r] = 0.0f;

    const int mat = lane >> 3;
    const int a_m = (mat & 1) * 8 + (lane & 7);
    const int a_k = (mat >> 1) * 8;
    const int w_n = (mat >> 1) * 8 + (lane & 7);
    const int w_k = (mat & 1) * 8;

    float4 pa0a, pa0b, pa1a, pa1b, pw0a, pw0b;
    {
        const float* pA0 = &A [(m0 +      lr) * EE + lkf];
        const float* pA1 = &A [(m0 + 64 + lr) * EE + lkf];
        const float* pW  = &Wm[(n0 +      lr) * EE + lkf];
        pa0a = *(const float4*)(pA0);     pa0b = *(const float4*)(pA0 + 4);
        pa1a = *(const float4*)(pA1);     pa1b = *(const float4*)(pA1 + 4);
        pw0a = *(const float4*)(pW);      pw0b = *(const float4*)(pW + 4);
    }

    for (int kt = 0; kt < 8; ++kt) {
        __syncthreads();
        cvt8store(&sA[0][lr * 40 + lkf],        &sA[1][lr * 40 + lkf],        pa0a, pa0b);
        cvt8store(&sA[0][(64 + lr) * 40 + lkf], &sA[1][(64 + lr) * 40 + lkf], pa1a, pa1b);
        cvt8store(&sW[0][lr * 40 + lkf],        &sW[1][lr * 40 + lkf],        pw0a, pw0b);
        __syncthreads();

        if (kt < 7) {
            const int k0 = (kt + 1) * 32;
            const float* pA0 = &A [(m0 +      lr) * EE + k0 + lkf];
            const float* pA1 = &A [(m0 + 64 + lr) * EE + k0 + lkf];
            const float* pW  = &Wm[(n0 +      lr) * EE + k0 + lkf];
            pa0a = *(const float4*)(pA0);     pa0b = *(const float4*)(pA0 + 4);
            pa1a = *(const float4*)(pA1);     pa1b = *(const float4*)(pA1 + 4);
            pw0a = *(const float4*)(pW);      pw0b = *(const float4*)(pW + 4);
        }

        #pragma unroll
        for (int ks = 0; ks < 2; ++ks) {
            unsigned ah[2][4], al[2][4], bh[4][2], bl[4][2];
            #pragma unroll
            for (int mt = 0; mt < 2; ++mt) {
                unsigned adr_h = (unsigned)__cvta_generic_to_shared(
                    &sA[0][(wm * 32 + mt * 16 + a_m) * 40 + ks * 16 + a_k]);
                unsigned adr_l = (unsigned)__cvta_generic_to_shared(
                    &sA[1][(wm * 32 + mt * 16 + a_m) * 40 + ks * 16 + a_k]);
                ldsm4(ah[mt], adr_h);
                ldsm4(al[mt], adr_l);
            }
            #pragma unroll
            for (int np = 0; np < 2; ++np) {
                unsigned t[4];
                unsigned adr_h = (unsigned)__cvta_generic_to_shared(
                    &sW[0][(wn * 32 + np * 16 + w_n) * 40 + ks * 16 + w_k]);
                ldsm4(t, adr_h);
                bh[np * 2][0] = t[0]; bh[np * 2][1] = t[1];
                bh[np * 2 + 1][0] = t[2]; bh[np * 2 + 1][1] = t[3];
                unsigned adr_l = (unsigned)__cvta_generic_to_shared(
                    &sW[1][(wn * 32 + np * 16 + w_n) * 40 + ks * 16 + w_k]);
                ldsm4(t, adr_l);
                bl[np * 2][0] = t[0]; bl[np * 2][1] = t[1];
                bl[np * 2 + 1][0] = t[2]; bl[np * 2 + 1][1] = t[3];
            }
            #pragma unroll
            for (int mt = 0; mt < 2; ++mt)
                #pragma unroll
                for (int nt = 0; nt < 4; ++nt) {
                    mma16816(acc[mt][nt], ah[mt], bh[nt]);
                    mma16816(acc[mt][nt], ah[mt], bl[nt]);
                    mma16816(acc[mt][nt], al[mt], bh[nt]);
                }
        }
    }

    float* out = (z == 0) ? g_Q : (z == 1) ? g_K : g_V;
    const float* bias = (z == 0) ? bq : (z == 1) ? bk : bv;
    #pragma unroll
    for (int nt = 0; nt < 4; ++nt) {
        const int n = n0 + wn * 32 + nt * 8 + (lane & 3) * 2;
        const float b0 = bias[n], b1 = bias[n + 1];
        #pragma unroll
        for (int mt = 0; mt < 2; ++mt) {
            const int m = m0 + wm * 32 + mt * 16 + (lane >> 2);
            float2 r0 = make_float2(acc[mt][nt][0] + b0, acc[mt][nt][1] + b1);
            float2 r1 = make_float2(acc[mt][nt][2] + b0, acc[mt][nt][3] + b1);
            *(float2*)&out[m * EE + n] = r0;
            *(float2*)&out[(m + 8) * EE + n] = r1;
        }
    }
}

// ---------------------------------------------------------------------------
// Kernel 2: AFT-local attention — occupancy-first rewrite.
// Tile 64 rows x 32 channels, 256 thr, __launch_bounds__(256,4) -> 4 CTAs/SM.
// 2-row pairing (il, il+2) kept; pos_bias moved to SMEM (pitch 67, conflict-
// free scalar LDS); row C's pb pair = carried copy of row A's previous pair.
// Body = peeled edges + rolled uniform middle loop (small I$ footprint).
// Unshifted softmax (provably no fp32 overflow).
// ---------------------------------------------------------------------------
template <int PAR, bool CHECK>
__device__ __forceinline__ void pair2s(
    const int il, const int j0, const int gq0,
    const float* __restrict__ Kc, const float* __restrict__ Vc,
    const float* __restrict__ pbc, const float px1, const float px63,
    float* __restrict__ out)
{
    const int A = il, C = il + 2;
    const float qA = g_Q[gq0 + A * EE] * LOG2E;
    const float qC = g_Q[gq0 + C * EE] * LOG2E;

    // boundary windows w=0 / w=64: K masked to 0 -> p = valid ? 1 : 0
    float denA, numA, denC, numC;
    {
        float vA0 = 1.f, vA6 = 1.f, vC0 = 1.f, vC6 = 1.f;
        if (CHECK) {
            vA0 = inbf(j0 + A); vA6 = inbf(j0 + A + 64);
            vC0 = inbf(j0 + C); vC6 = inbf(j0 + C + 64);
        }
        denA = vA0 + vA6;  numA = Vc[A] + Vc[A + 64];
        denC = vC0 + vC6;  numC = Vc[C] + Vc[C + 64];
    }

    if (PAR == 0) {   // A's w=1 at r=il+1 (not covered by even-aligned pairs)
        float p = ex2f(qA * (Kc[il + 1] + px1));
        if (CHECK) p *= inbf(j0 + il + 1);
        denA += p; numA = fmaf(p, Vc[il + 1], numA);
    }

    const int rbase = il + 2 - PAR;              // even
    float pA0 = pbc[2 - PAR], pA1 = pbc[3 - PAR];
    float pC0, pC1;

    // ---- t = 0: A full pair; C edge ----
    {
        const float2 k2 = *(const float2*)&Kc[rbase];
        const float2 v2 = *(const float2*)&Vc[rbase];
        float m0 = 1.f, m1 = 1.f;
        if (CHECK) { m0 = inbf(j0 + rbase); m1 = inbf(j0 + rbase + 1); }
        float p0 = ex2f(qA * (k2.x + pA0));
        float p1 = ex2f(qA * (k2.y + pA1));
        if (CHECK) { p0 *= m0; p1 *= m1; }
        denA += p0 + p1;
        numA = fmaf(p0, v2.x, numA);
        numA = fmaf(p1, v2.y, numA);
        if (PAR == 0) {   // C's w'=1 on lane1 (r = rbase+1 = il+3)
            float p = ex2f(qC * (k2.y + px1));
            if (CHECK) p *= m1;
            denC += p; numC = fmaf(p, v2.y, numC);
        }
        pC0 = pA0; pC1 = pA1;
        pA0 = pbc[4 - PAR]; pA1 = pbc[5 - PAR];
    }

    // ---- middle t = 1..30: both rows full pairs (uniform, rolled) ----
    #pragma unroll 6
    for (int t = 1; t <= 30; ++t) {
        const int r = rbase + 2 * t;
        const float2 k2 = *(const float2*)&Kc[r];
        const float2 v2 = *(const float2*)&Vc[r];
        float m0 = 1.f, m1 = 1.f;
        if (CHECK) { m0 = inbf(j0 + r); m1 = inbf(j0 + r + 1); }
        float pa0 = ex2f(qA * (k2.x + pA0));
        float pa1 = ex2f(qA * (k2.y + pA1));
        float pc0 = ex2f(qC * (k2.x + pC0));
        float pc1 = ex2f(qC * (k2.y + pC1));
        if (CHECK) { pa0 *= m0; pa1 *= m1; pc0 *= m0; pc1 *= m1; }
        denA += pa0 + pa1;
        denC += pc0 + pc1;
        numA = fmaf(pa0, v2.x, numA);  numA = fmaf(pa1, v2.y, numA);
        numC = fmaf(pc0, v2.x, numC);  numC = fmaf(pc1, v2.y, numC);
        pC0 = pA0; pC1 = pA1;
        const int wN = 2 - PAR + 2 * t + 2;      // next A pair (pad slots make
        pA0 = pbc[wN]; pA1 = pbc[wN + 1];        // the t=30 overread safe+unused)
    }

    // ---- tail ----
    if (PAR == 0) {
        // t=31: A none (w=64 is boundary); C full pair (62,63) via carried pC
        const int r = rbase + 62;                // il + 64
        const float2 k2 = *(const float2*)&Kc[r];
        const float2 v2 = *(const float2*)&Vc[r];
        float m0 = 1.f, m1 = 1.f;
        if (CHECK) { m0 = inbf(j0 + r); m1 = inbf(j0 + r + 1); }
        float pc0 = ex2f(qC * (k2.x + pC0));
        float pc1 = ex2f(qC * (k2.y + pC1));
        if (CHECK) { pc0 *= m0; pc1 *= m1; }
        denC += pc0 + pc1;
        numC = fmaf(pc0, v2.x, numC);
        numC = fmaf(pc1, v2.y, numC);
    } else {
        // t=31: A single w=63 (lane0, px63); C full pair (61,62) via carried pC
        const int r = rbase + 62;                // il + 63
        const float2 k2 = *(const float2*)&Kc[r];
        const float2 v2 = *(const float2*)&Vc[r];
        float m0 = 1.f, m1 = 1.f;
        if (CHECK) { m0 = inbf(j0 + r); m1 = inbf(j0 + r + 1); }
        float pa = ex2f(qA * (k2.x + px63));
        if (CHECK) pa *= m0;
        denA += pa; numA = fmaf(pa, v2.x, numA);
        float pc0 = ex2f(qC * (k2.x + pC0));
        float pc1 = ex2f(qC * (k2.y + pC1));
        if (CHECK) { pc0 *= m0; pc1 *= m1; }
        denC += pc0 + pc1;
        numC = fmaf(pc0, v2.x, numC);
        numC = fmaf(pc1, v2.y, numC);
        // t=32: C single w=63 (lane0, px63) at r = il + 65
        const int r2 = rbase + 64;
        const float kx = Kc[r2], vx = Vc[r2];
        float p = ex2f(qC * (kx + px63));
        if (CHECK) p *= inbf(j0 + r2);
        denC += p; numC = fmaf(p, vx, numC);
    }

    const float sA = rcpf(1.0f + ex2f(-qA));     // sigmoid(Q)
    const float sC = rcpf(1.0f + ex2f(-qC));
    out[gq0 + A * EE] = sA * sA * numA * rcpf(denA);
    out[gq0 + C * EE] = sC * sC * numC * rcpf(denC);
}

__global__ __launch_bounds__(256, 4) void aft_local(
    const float* __restrict__ pos_bias,   // [65][256]
    float* __restrict__ out)              // [B][L][E]
{
    extern __shared__ float smem[];
    float* Kt = smem;                     // [32 ch][PITCH2 rows]
    float* Vt = smem + 32 * PITCH2;
    float* Pb = smem + 64 * PITCH2;       // [32 ch][PBPITCH]

    const int tid = threadIdx.x;
    const int c   = tid & 31;             // channel within block (lane)
    const int g   = tid >> 5;             // 0..7: 8-row group
    const int e0  = blockIdx.x * 32;
    const int i0  = blockIdx.y * 64;
    const int bi  = blockIdx.z;
    const int e   = e0 + c;
    const int j0  = i0 - 32;

    // Fill transposed K/V tiles: rows r=0..127 (j = j0+r), zero-fill OOB.
    for (int idx = tid; idx < 128 * 8; idx += 256) {
        const int r  = idx >> 3;
        const int cc = (idx & 7) << 2;
        const int j  = j0 + r;
        float4 kv = make_float4(0.f, 0.f, 0.f, 0.f);
        float4 vv = make_float4(0.f, 0.f, 0.f, 0.f);
        if ((unsigned)j < (unsigned)LL) {
            const int off = (bi * LL + j) * EE + e0 + cc;
            kv = *(const float4*)&g_K[off];
            vv = *(const float4*)&g_V[off];
        }
        Kt[(cc + 0) * PITCH2 + r] = kv.x;  Kt[(cc + 1) * PITCH2 + r] = kv.y;
        Kt[(cc + 2) * PITCH2 + r] = kv.z;  Kt[(cc + 3) * PITCH2 + r] = kv.w;
        Vt[(cc + 0) * PITCH2 + r] = vv.x;  Vt[(cc + 1) * PITCH2 + r] = vv.y;
        Vt[(cc + 2) * PITCH2 + r] = vv.z;  Vt[(cc + 3) * PITCH2 + r] = vv.w;
    }

    // Fill pos_bias tile: Pb[c][w], w = 0..64 (pad slots 65,66 unused).
    for (int idx = tid; idx < 65 * 32; idx += 256) {
        const int w  = idx >> 5;
        const int ci = idx & 31;
        Pb[ci * PBPITCH + w] = pos_bias[w * EE + e0 + ci];
    }
    __syncthreads();

    const float* Kc  = &Kt[c * PITCH2];
    const float* Vc  = &Vt[c * PITCH2];
    const float* pbc = &Pb[c * PBPITCH];
    const float px1  = pbc[1], px63 = pbc[63];
    const int   gq0  = (bi * LL + i0) * EE + e;

    const bool interior = (i0 >= 32) && (i0 + 96 <= LL);
    if (interior) {
        #pragma unroll 1
        for (int h = 0; h < 2; ++h) {
            const int ib = 8 * g + 4 * h;
            pair2s<0, false>(ib,     j0, gq0, Kc, Vc, pbc, px1, px63, out);
            pair2s<1, false>(ib + 1, j0, gq0, Kc, Vc, pbc, px1, px63, out);
        }
    } else {
        #pragma unroll 1
        for (int h = 0; h < 2; ++h) {
            const int ib = 8 * g + 4 * h;
            pair2s<0, true>(ib,     j0, gq0, Kc, Vc, pbc, px1, px63, out);
            pair2s<1, true>(ib + 1, j0, gq0, Kc, Vc, pbc, px1, px63, out);
        }
    }
}

// ---------------------------------------------------------------------------
// launch
// ---------------------------------------------------------------------------
extern "C" void kernel_launch(void* const* d_in, const int* in_sizes, int n_in,
                              void* d_out, int out_size)
{
    const float* q  = (const float*)d_in[0];
    const float* Wq = (const float*)d_in[1];
    const float* bq = (const float*)d_in[2];
    const float* Wk = (const float*)d_in[3];
    const float* bk = (const float*)d_in[4];
    const float* Wv = (const float*)d_in[5];
    const float* bv = (const float*)d_in[6];
    const float* pb = (const float*)d_in[7];
    float* out = (float*)d_out;

    (void)in_sizes; (void)n_in; (void)out_size;

    // 1: QKV projection on tensor cores (fp32->bf16 hi/lo split fused in-load)
    dim3 gg(32, 4, 3);
    qkv_mma<<<gg, 256>>>(q, Wq, Wk, Wv, bq, bk, bv);

    // 2: AFT local attention — 41.9KB dynamic smem (< 48KB default, 4 CTAs/SM)
    const int aft_smem = (64 * PITCH2 + 32 * PBPITCH) * 4;
    dim3 ga(EE / 32, LL / 64, BB);
    aft_local<<<ga, 256, aft_smem>>>(pb, out);
}